// round 6
// baseline (speedup 1.0000x reference)
#include <cuda_runtime.h>

#define DIM 8
typedef unsigned int u32;
typedef unsigned long long u64;

// packed f32x2 helpers (sm_103a)
__device__ __forceinline__ u64 pk2(float lo, float hi) {
    u64 r; asm("mov.b64 %0,{%1,%2};" : "=l"(r) : "f"(lo), "f"(hi)); return r;
}
__device__ __forceinline__ void upk2(u64 v, float& lo, float& hi) {
    asm("mov.b64 {%0,%1},%2;" : "=f"(lo), "=f"(hi) : "l"(v));
}
__device__ __forceinline__ u64 add2(u64 a, u64 b) {
    u64 r; asm("add.rn.f32x2 %0,%1,%2;" : "=l"(r) : "l"(a), "l"(b)); return r;
}

// read-only (non-coherent) 128-bit load
__device__ __forceinline__ float4 ldnc4(const float4* p) {
    float4 v;
    asm("ld.global.nc.v4.f32 {%0,%1,%2,%3},[%4];"
        : "=f"(v.x), "=f"(v.y), "=f"(v.z), "=f"(v.w) : "l"(p));
    return v;
}

// One E8 row decode: hot analytic path + inline bit-exact fallback.
// Fully unrolled, constant indices only — stays entirely in registers.
__device__ __forceinline__ void e8_row(const float x[DIM], float r[DIM]) {
    const u64 MAG2  = 0x4B4000004B400000ull;  // {12582912, 12582912}
    const u64 NMAG2 = 0xCB400000CB400000ull;

    float t[DIM], f[DIM], d[DIM];
#pragma unroll
    for (int p = 0; p < 4; ++p) {
        u64 xp = pk2(x[2 * p], x[2 * p + 1]);
        u64 tp = add2(xp, MAG2);     // mantissa LSB = parity(round(x))
        u64 fp = add2(tp, NMAG2);    // f = round-half-even(x), exact
        upk2(tp, t[2 * p], t[2 * p + 1]);
        upk2(fp, f[2 * p], f[2 * p + 1]);
    }
#pragma unroll
    for (int i = 0; i < DIM; ++i) d[i] = x[i] - f[i];  // exact

    u32 tb[DIM], db[DIM];
#pragma unroll
    for (int i = 0; i < DIM; ++i) {
        tb[i] = __float_as_uint(t[i]);
        db[i] = __float_as_uint(d[i]);
    }

    // argmax|d| / argmin|d|, first-occurrence ties
    float amax = fabsf(d[0]), amin = amax;
    int imax = 0, imin = 0;
#pragma unroll
    for (int i = 1; i < DIM; ++i) {
        float ad = fabsf(d[i]);
        imax = (ad > amax) ? i : imax;  amax = fmaxf(amax, ad);
        imin = (ad < amin) ? i : imin;  amin = fminf(amin, ad);
    }

    u32 T  = (tb[0] ^ tb[1]) ^ (tb[2] ^ tb[3]) ^ ((tb[4] ^ tb[5]) ^ (tb[6] ^ tb[7]));
    u32 SG = (db[0] ^ db[1]) ^ (db[2] ^ db[3]) ^ ((db[4] ^ db[5]) ^ (db[6] ^ db[7]));
    const bool odd0 = (T & 1u) != 0u;
    const bool odd1 = ((T ^ (SG >> 31)) & 1u) != 0u;

    float Asum = ((fabsf(d[0]) + fabsf(d[1])) + (fabsf(d[2]) + fabsf(d[3]))) +
                 ((fabsf(d[4]) + fabsf(d[5])) + (fabsf(d[6]) + fabsf(d[7])));

    // dist1 - dist0 = 2 - sum|d| + odd1*2*min|d| - odd0*(1 - 2*max|d|)
    float s0 = odd0 ? __fmaf_rn(-2.0f, amax, 1.0f) : 0.0f;
    float s1 = odd1 ? (amin + amin) : 0.0f;
    float Dd = ((2.0f - Asum) + s1) - s0;

    if ((amin < 2e-6f) || (amin == 0.5f) || (fabsf(Dd) < 1e-5f)) {
        // Bit-exact reference recompute (rare: ~1e-4 of rows).
        float c0[DIM];
#pragma unroll
        for (int i = 0; i < DIM; ++i) {
            float step = (d[i] >= 0.0f) ? 1.0f : -1.0f;
            c0[i] = f[i] + ((odd0 && i == imax) ? step : 0.0f);
        }
        float y[DIM], f1[DIM], d1[DIM];
        int isum1 = 0;
#pragma unroll
        for (int i = 0; i < DIM; ++i) {
            y[i]  = x[i] - 0.5f;
            f1[i] = rintf(y[i]);
            d1[i] = y[i] - f1[i];
            isum1 += __float2int_rn(f1[i]);
        }
        int w1 = 0;
        float b1 = fabsf(d1[0]);
#pragma unroll
        for (int i = 1; i < DIM; ++i) {
            float ad = fabsf(d1[i]);
            if (ad > b1) { b1 = ad; w1 = i; }
        }
        const bool o1 = (isum1 & 1) != 0;
        float c1[DIM];
#pragma unroll
        for (int i = 0; i < DIM; ++i) {
            float step = (d1[i] >= 0.0f) ? 1.0f : -1.0f;
            c1[i] = (f1[i] + ((o1 && i == w1) ? step : 0.0f)) + 0.5f;
        }
        float s0q = 0.0f, s1q = 0.0f;
#pragma unroll
        for (int i = 0; i < DIM; ++i) {
            float e0 = x[i] - c0[i];
            float e1 = x[i] - c1[i];
            s0q = __fmaf_rn(e0, e0, s0q);
            s1q = __fmaf_rn(e1, e1, s1q);
        }
        const bool tk0 = (s0q <= s1q);
#pragma unroll
        for (int i = 0; i < DIM; ++i) r[i] = tk0 ? c0[i] : c1[i];
    } else {
        const bool take0 = (Dd >= 0.0f);
        int wsel = take0 ? (odd0 ? imax : 8) : (odd1 ? imin : 8);
        float kb = take0 ? 0.0f : 1.0f;
        float kf = take0 ? 2.0f : -1.0f;
#pragma unroll
        for (int i = 0; i < DIM; ++i) {
            float cs  = __uint_as_float((db[i] & 0x80000000u) | 0x3F000000u);
            float kap = (i == wsel) ? kf : kb;
            r[i] = __fmaf_rn(cs, kap, f[i]);
        }
    }
}

// 2 rows per thread, 4 front-batched read-only LDG.128, default stores.
__global__ void __launch_bounds__(256)
e8_closest_kernel(const float4* __restrict__ xin, float4* __restrict__ outv, int n_rows) {
    int tid = blockIdx.x * blockDim.x + threadIdx.x;
    size_t r0 = 2 * (size_t)tid;
    size_t r1 = r0 + 1;
    if ((int)r0 >= n_rows) return;
    const bool has2 = ((int)r1 < n_rows);

    // Front-batched loads (MLP_p1 = 4)
    float4 A0 = ldnc4(xin + 2 * r0);
    float4 B0 = ldnc4(xin + 2 * r0 + 1);
    float4 A1 = has2 ? ldnc4(xin + 2 * r1)     : make_float4(0, 0, 0, 0);
    float4 B1 = has2 ? ldnc4(xin + 2 * r1 + 1) : make_float4(0, 0, 0, 0);

    {
        float x[DIM] = {A0.x, A0.y, A0.z, A0.w, B0.x, B0.y, B0.z, B0.w};
        float r[DIM];
        e8_row(x, r);
        outv[2 * r0]     = make_float4(r[0], r[1], r[2], r[3]);
        outv[2 * r0 + 1] = make_float4(r[4], r[5], r[6], r[7]);
    }
    if (has2) {
        float x[DIM] = {A1.x, A1.y, A1.z, A1.w, B1.x, B1.y, B1.z, B1.w};
        float r[DIM];
        e8_row(x, r);
        outv[2 * r1]     = make_float4(r[0], r[1], r[2], r[3]);
        outv[2 * r1 + 1] = make_float4(r[4], r[5], r[6], r[7]);
    }
}

extern "C" void kernel_launch(void* const* d_in, const int* in_sizes, int n_in,
                              void* d_out, int out_size) {
    const float4* x = (const float4*)d_in[0];
    float4* out = (float4*)d_out;
    const int n_rows = in_sizes[0] / DIM;
    const int threads = 256;
    const int rows_per_block = threads * 2;
    const int blocks = (n_rows + rows_per_block - 1) / rows_per_block;
    e8_closest_kernel<<<blocks, threads>>>(x, out, n_rows);
}

// round 7
// speedup vs baseline: 1.0066x; 1.0066x over previous
#include <cuda_runtime.h>

#define DIM 8
typedef unsigned int u32;
typedef unsigned long long u64;

// packed f32x2 helpers (sm_103a)
__device__ __forceinline__ u64 pk2(float lo, float hi) {
    u64 r; asm("mov.b64 %0,{%1,%2};" : "=l"(r) : "f"(lo), "f"(hi)); return r;
}
__device__ __forceinline__ void upk2(u64 v, float& lo, float& hi) {
    asm("mov.b64 {%0,%1},%2;" : "=f"(lo), "=f"(hi) : "l"(v));
}
__device__ __forceinline__ u64 add2(u64 a, u64 b) {
    u64 r; asm("add.rn.f32x2 %0,%1,%2;" : "=l"(r) : "l"(a), "l"(b)); return r;
}

// 256-bit global load/store (sm_100a+: LDG.E.256 / STG.E.256).
// Row stride is 32 B and the base is 256B-aligned, so every access is
// 32B-aligned as required.
__device__ __forceinline__ void ldg256(const float* p, float v[8]) {
    u32 a0, a1, a2, a3, a4, a5, a6, a7;
    asm("ld.global.nc.v8.b32 {%0,%1,%2,%3,%4,%5,%6,%7},[%8];"
        : "=r"(a0), "=r"(a1), "=r"(a2), "=r"(a3),
          "=r"(a4), "=r"(a5), "=r"(a6), "=r"(a7)
        : "l"(p));
    v[0] = __uint_as_float(a0); v[1] = __uint_as_float(a1);
    v[2] = __uint_as_float(a2); v[3] = __uint_as_float(a3);
    v[4] = __uint_as_float(a4); v[5] = __uint_as_float(a5);
    v[6] = __uint_as_float(a6); v[7] = __uint_as_float(a7);
}
__device__ __forceinline__ void stg256(float* p, const float v[8]) {
    asm("st.global.v8.b32 [%0],{%1,%2,%3,%4,%5,%6,%7,%8};"
        :: "l"(p),
           "r"(__float_as_uint(v[0])), "r"(__float_as_uint(v[1])),
           "r"(__float_as_uint(v[2])), "r"(__float_as_uint(v[3])),
           "r"(__float_as_uint(v[4])), "r"(__float_as_uint(v[5])),
           "r"(__float_as_uint(v[6])), "r"(__float_as_uint(v[7])));
}

__global__ void __launch_bounds__(256)
e8_closest_kernel(const float* __restrict__ xin, float* __restrict__ outv, int n_rows) {
    int row = blockIdx.x * blockDim.x + threadIdx.x;
    if (row >= n_rows) return;

    float x[DIM];
    ldg256(xin + (size_t)row * DIM, x);

    // Round-half-even via magic constant (bitwise == rintf for |x| < 2^22).
    // Low mantissa bit of t gives parity of f. All ops exact. Packed f32x2.
    const u64 MAG2  = 0x4B4000004B400000ull;  // {12582912, 12582912}
    const u64 NMAG2 = 0xCB400000CB400000ull;

    float t[DIM], f[DIM], d[DIM];
#pragma unroll
    for (int p = 0; p < 4; ++p) {
        u64 xp = pk2(x[2 * p], x[2 * p + 1]);
        u64 tp = add2(xp, MAG2);     // mantissa LSB = parity(round(x))
        u64 fp = add2(tp, NMAG2);    // f = round-half-even(x), exact
        upk2(tp, t[2 * p], t[2 * p + 1]);
        upk2(fp, f[2 * p], f[2 * p + 1]);
    }
#pragma unroll
    for (int i = 0; i < DIM; ++i) d[i] = x[i] - f[i];  // exact residual

    u32 tb[DIM], db[DIM];
#pragma unroll
    for (int i = 0; i < DIM; ++i) {
        tb[i] = __float_as_uint(t[i]);
        db[i] = __float_as_uint(d[i]);
    }

    // argmax|d| / argmin|d|, first-occurrence ties (matches jnp.argmax)
    float amax = fabsf(d[0]), amin = amax;
    int imax = 0, imin = 0;
#pragma unroll
    for (int i = 1; i < DIM; ++i) {
        float ad = fabsf(d[i]);
        imax = (ad > amax) ? i : imax;  amax = fmaxf(amax, ad);
        imin = (ad < amin) ? i : imin;  amin = fminf(amin, ad);
    }

    // parity(sum f) from magic-add LSBs; coset-1 parity flips per negative d
    u32 T  = (tb[0] ^ tb[1]) ^ (tb[2] ^ tb[3]) ^ ((tb[4] ^ tb[5]) ^ (tb[6] ^ tb[7]));
    u32 SG = (db[0] ^ db[1]) ^ (db[2] ^ db[3]) ^ ((db[4] ^ db[5]) ^ (db[6] ^ db[7]));
    const bool odd0 = (T & 1u) != 0u;
    const bool odd1 = ((T ^ (SG >> 31)) & 1u) != 0u;

    float Asum = ((fabsf(d[0]) + fabsf(d[1])) + (fabsf(d[2]) + fabsf(d[3]))) +
                 ((fabsf(d[4]) + fabsf(d[5])) + (fabsf(d[6]) + fabsf(d[7])));

    // dist1 - dist0 = 2 - sum|d| + odd1*2*min|d| - odd0*(1 - 2*max|d|)
    float s0 = odd0 ? __fmaf_rn(-2.0f, amax, 1.0f) : 0.0f;
    float s1 = odd1 ? (amin + amin) : 0.0f;
    float Dd = ((2.0f - Asum) + s1) - s0;

    float r[DIM];

    // Guards: d==0 / near-tie rounding zone, all-|d|==0.5 ambiguity, and
    // too-close coset decision -> bit-exact reference recompute (~1e-4 rows).
    if ((amin < 2e-6f) || (amin == 0.5f) || (fabsf(Dd) < 1e-5f)) {
        float c0[DIM];
#pragma unroll
        for (int i = 0; i < DIM; ++i) {
            float step = (d[i] >= 0.0f) ? 1.0f : -1.0f;
            c0[i] = f[i] + ((odd0 && i == imax) ? step : 0.0f);
        }
        float y[DIM], f1[DIM], d1[DIM];
        int isum1 = 0;
#pragma unroll
        for (int i = 0; i < DIM; ++i) {
            y[i]  = x[i] - 0.5f;
            f1[i] = rintf(y[i]);
            d1[i] = y[i] - f1[i];
            isum1 += __float2int_rn(f1[i]);
        }
        int w1 = 0;
        float b1 = fabsf(d1[0]);
#pragma unroll
        for (int i = 1; i < DIM; ++i) {
            float ad = fabsf(d1[i]);
            if (ad > b1) { b1 = ad; w1 = i; }
        }
        const bool o1 = (isum1 & 1) != 0;
        float c1[DIM];
#pragma unroll
        for (int i = 0; i < DIM; ++i) {
            float step = (d1[i] >= 0.0f) ? 1.0f : -1.0f;
            c1[i] = (f1[i] + ((o1 && i == w1) ? step : 0.0f)) + 0.5f;
        }
        float s0q = 0.0f, s1q = 0.0f;
#pragma unroll
        for (int i = 0; i < DIM; ++i) {
            float e0 = x[i] - c0[i];
            float e1 = x[i] - c1[i];
            s0q = __fmaf_rn(e0, e0, s0q);
            s1q = __fmaf_rn(e1, e1, s1q);
        }
        const bool tk0 = (s0q <= s1q);
#pragma unroll
        for (int i = 0; i < DIM; ++i) r[i] = tk0 ? c0[i] : c1[i];
    } else {
        const bool take0 = (Dd >= 0.0f);  // d0 <= d1 -> coset 0
        int wsel = take0 ? (odd0 ? imax : 8) : (odd1 ? imin : 8);
        // answer coord = f + kappa * copysign(0.5, d):
        //   coset0: 0 normal, 2 flipped; coset1: 1 normal, -1 flipped
        float kb = take0 ? 0.0f : 1.0f;
        float kf = take0 ? 2.0f : -1.0f;
#pragma unroll
        for (int i = 0; i < DIM; ++i) {
            float cs  = __uint_as_float((db[i] & 0x80000000u) | 0x3F000000u);
            float kap = (i == wsel) ? kf : kb;
            r[i] = __fmaf_rn(cs, kap, f[i]);
        }
    }

    stg256(outv + (size_t)row * DIM, r);
}

extern "C" void kernel_launch(void* const* d_in, const int* in_sizes, int n_in,
                              void* d_out, int out_size) {
    const float* x = (const float*)d_in[0];
    float* out = (float*)d_out;
    const int n_rows = in_sizes[0] / DIM;
    const int threads = 256;
    const int blocks = (n_rows + threads - 1) / threads;
    e8_closest_kernel<<<blocks, threads>>>(x, out, n_rows);
}

// round 8
// speedup vs baseline: 1.0499x; 1.0430x over previous
#include <cuda_runtime.h>

#define DIM 8
typedef unsigned int u32;
typedef unsigned long long u64;

// packed f32x2 helpers (sm_103a)
__device__ __forceinline__ u64 pk2(float lo, float hi) {
    u64 r; asm("mov.b64 %0,{%1,%2};" : "=l"(r) : "f"(lo), "f"(hi)); return r;
}
__device__ __forceinline__ void upk2(u64 v, float& lo, float& hi) {
    asm("mov.b64 {%0,%1},%2;" : "=f"(lo), "=f"(hi) : "l"(v));
}
__device__ __forceinline__ u64 add2(u64 a, u64 b) {
    u64 r; asm("add.rn.f32x2 %0,%1,%2;" : "=l"(r) : "l"(a), "l"(b)); return r;
}

// 256-bit global load/store (sm_100a+: LDG.E.256 / STG.E.256)
__device__ __forceinline__ void ldg256(const float* p, float v[8]) {
    u32 a0, a1, a2, a3, a4, a5, a6, a7;
    asm("ld.global.nc.v8.b32 {%0,%1,%2,%3,%4,%5,%6,%7},[%8];"
        : "=r"(a0), "=r"(a1), "=r"(a2), "=r"(a3),
          "=r"(a4), "=r"(a5), "=r"(a6), "=r"(a7)
        : "l"(p));
    v[0] = __uint_as_float(a0); v[1] = __uint_as_float(a1);
    v[2] = __uint_as_float(a2); v[3] = __uint_as_float(a3);
    v[4] = __uint_as_float(a4); v[5] = __uint_as_float(a5);
    v[6] = __uint_as_float(a6); v[7] = __uint_as_float(a7);
}
__device__ __forceinline__ void stg256(float* p, const float v[8]) {
    asm("st.global.v8.b32 [%0],{%1,%2,%3,%4,%5,%6,%7,%8};"
        :: "l"(p),
           "r"(__float_as_uint(v[0])), "r"(__float_as_uint(v[1])),
           "r"(__float_as_uint(v[2])), "r"(__float_as_uint(v[3])),
           "r"(__float_as_uint(v[4])), "r"(__float_as_uint(v[5])),
           "r"(__float_as_uint(v[6])), "r"(__float_as_uint(v[7])));
}

// One E8 row decode: hot analytic path + inline bit-exact fallback.
__device__ __forceinline__ void e8_row(const float x[DIM], float r[DIM]) {
    const u64 MAG2  = 0x4B4000004B400000ull;  // {12582912, 12582912}
    const u64 NMAG2 = 0xCB400000CB400000ull;

    float t[DIM], f[DIM], d[DIM];
#pragma unroll
    for (int p = 0; p < 4; ++p) {
        u64 xp = pk2(x[2 * p], x[2 * p + 1]);
        u64 tp = add2(xp, MAG2);     // mantissa LSB = parity(round(x))
        u64 fp = add2(tp, NMAG2);    // f = round-half-even(x), exact
        upk2(tp, t[2 * p], t[2 * p + 1]);
        upk2(fp, f[2 * p], f[2 * p + 1]);
    }
#pragma unroll
    for (int i = 0; i < DIM; ++i) d[i] = x[i] - f[i];  // exact residual

    u32 tb[DIM], db[DIM];
#pragma unroll
    for (int i = 0; i < DIM; ++i) {
        tb[i] = __float_as_uint(t[i]);
        db[i] = __float_as_uint(d[i]);
    }

    float amax = fabsf(d[0]), amin = amax;
    int imax = 0, imin = 0;
#pragma unroll
    for (int i = 1; i < DIM; ++i) {
        float ad = fabsf(d[i]);
        imax = (ad > amax) ? i : imax;  amax = fmaxf(amax, ad);
        imin = (ad < amin) ? i : imin;  amin = fminf(amin, ad);
    }

    u32 T  = (tb[0] ^ tb[1]) ^ (tb[2] ^ tb[3]) ^ ((tb[4] ^ tb[5]) ^ (tb[6] ^ tb[7]));
    u32 SG = (db[0] ^ db[1]) ^ (db[2] ^ db[3]) ^ ((db[4] ^ db[5]) ^ (db[6] ^ db[7]));
    const bool odd0 = (T & 1u) != 0u;
    const bool odd1 = ((T ^ (SG >> 31)) & 1u) != 0u;

    float Asum = ((fabsf(d[0]) + fabsf(d[1])) + (fabsf(d[2]) + fabsf(d[3]))) +
                 ((fabsf(d[4]) + fabsf(d[5])) + (fabsf(d[6]) + fabsf(d[7])));

    // dist1 - dist0 = 2 - sum|d| + odd1*2*min|d| - odd0*(1 - 2*max|d|)
    float s0 = odd0 ? __fmaf_rn(-2.0f, amax, 1.0f) : 0.0f;
    float s1 = odd1 ? (amin + amin) : 0.0f;
    float Dd = ((2.0f - Asum) + s1) - s0;

    if ((amin < 2e-6f) || (amin == 0.5f) || (fabsf(Dd) < 1e-5f)) {
        // Bit-exact reference recompute (rare: ~1e-4 of rows).
        float c0[DIM];
#pragma unroll
        for (int i = 0; i < DIM; ++i) {
            float step = (d[i] >= 0.0f) ? 1.0f : -1.0f;
            c0[i] = f[i] + ((odd0 && i == imax) ? step : 0.0f);
        }
        float y[DIM], f1[DIM], d1[DIM];
        int isum1 = 0;
#pragma unroll
        for (int i = 0; i < DIM; ++i) {
            y[i]  = x[i] - 0.5f;
            f1[i] = rintf(y[i]);
            d1[i] = y[i] - f1[i];
            isum1 += __float2int_rn(f1[i]);
        }
        int w1 = 0;
        float b1 = fabsf(d1[0]);
#pragma unroll
        for (int i = 1; i < DIM; ++i) {
            float ad = fabsf(d1[i]);
            if (ad > b1) { b1 = ad; w1 = i; }
        }
        const bool o1 = (isum1 & 1) != 0;
        float c1[DIM];
#pragma unroll
        for (int i = 0; i < DIM; ++i) {
            float step = (d1[i] >= 0.0f) ? 1.0f : -1.0f;
            c1[i] = (f1[i] + ((o1 && i == w1) ? step : 0.0f)) + 0.5f;
        }
        float s0q = 0.0f, s1q = 0.0f;
#pragma unroll
        for (int i = 0; i < DIM; ++i) {
            float e0 = x[i] - c0[i];
            float e1 = x[i] - c1[i];
            s0q = __fmaf_rn(e0, e0, s0q);
            s1q = __fmaf_rn(e1, e1, s1q);
        }
        const bool tk0 = (s0q <= s1q);
#pragma unroll
        for (int i = 0; i < DIM; ++i) r[i] = tk0 ? c0[i] : c1[i];
    } else {
        const bool take0 = (Dd >= 0.0f);
        int wsel = take0 ? (odd0 ? imax : 8) : (odd1 ? imin : 8);
        float kb = take0 ? 0.0f : 1.0f;
        float kf = take0 ? 2.0f : -1.0f;
#pragma unroll
        for (int i = 0; i < DIM; ++i) {
            float cs  = __uint_as_float((db[i] & 0x80000000u) | 0x3F000000u);
            float kap = (i == wsel) ? kf : kb;
            r[i] = __fmaf_rn(cs, kap, f[i]);
        }
    }
}

// 2 rows per thread, 2 front-batched LDG.256, 2 STG.256.
// Consecutive threads handle consecutive row pairs -> each warp covers
// 4 KB contiguous per load batch (HBM row-buffer friendly).
__global__ void __launch_bounds__(256)
e8_closest_kernel(const float* __restrict__ xin, float* __restrict__ outv, int n_rows) {
    int tid = blockIdx.x * blockDim.x + threadIdx.x;
    int r0 = 2 * tid;
    int r1 = r0 + 1;
    if (r0 >= n_rows) return;
    const bool has2 = (r1 < n_rows);

    float x0[DIM], x1[DIM];
    ldg256(xin + (size_t)r0 * DIM, x0);
    if (has2) ldg256(xin + (size_t)r1 * DIM, x1);

    float o0[DIM];
    e8_row(x0, o0);
    stg256(outv + (size_t)r0 * DIM, o0);

    if (has2) {
        float o1[DIM];
        e8_row(x1, o1);
        stg256(outv + (size_t)r1 * DIM, o1);
    }
}

extern "C" void kernel_launch(void* const* d_in, const int* in_sizes, int n_in,
                              void* d_out, int out_size) {
    const float* x = (const float*)d_in[0];
    float* out = (float*)d_out;
    const int n_rows = in_sizes[0] / DIM;
    const int threads = 256;
    const int rows_per_block = threads * 2;
    const int blocks = (n_rows + rows_per_block - 1) / rows_per_block;
    e8_closest_kernel<<<blocks, threads>>>(x, out, n_rows);
}